// round 16
// baseline (speedup 1.0000x reference)
#include <cuda_runtime.h>
#include <cuda_fp16.h>
#include <cstdint>

// Winograd F(2x2,3x3): N=16, C=128, O=128, H=W=112, pad=1
#define NB 16
#define CD 128
#define OD 128
#define HH 112
#define NT 56
#define TPI (NT*NT)            // 3136 tiles per image
#define TILES (NB*TPI)         // 50176 total tiles

// Scratch (allocation-free): U fp16 only. V lives in SMEM.
__device__ unsigned short g_Uh[16 * OD * 128];            // 512 KB U[p][o][c]

__device__ __forceinline__ uint32_t smem_to_u32(const void* p) {
    uint32_t a;
    asm("{ .reg .u64 t; cvta.to.shared.u64 t, %1; cvt.u32.u64 %0, t; }" : "=r"(a) : "l"(p));
    return a;
}

// ldmatrix x4 (sm_75+)
#define LDSM4(r, addr) \
    asm volatile("ldmatrix.sync.aligned.m8n8.x4.shared.b16 {%0,%1,%2,%3}, [%4];" \
        : "=r"((r)[0]), "=r"((r)[1]), "=r"((r)[2]), "=r"((r)[3]) : "r"(addr))

// fp16 HMMA with fp32 accumulate (sm_80+)
#define MMA_F16(d, a, b) \
    asm volatile("mma.sync.aligned.m16n8k16.row.col.f32.f16.f16.f32 " \
        "{%0,%1,%2,%3},{%4,%5,%6,%7},{%8,%9},{%0,%1,%2,%3};" \
        : "+f"((d)[0]), "+f"((d)[1]), "+f"((d)[2]), "+f"((d)[3]) \
        : "r"((a)[0]), "r"((a)[1]), "r"((a)[2]), "r"((a)[3]), \
          "r"((b)[0]), "r"((b)[1]))

// cp.async (sm_80+)
#define CP16(dst, src) \
    asm volatile("cp.async.cg.shared.global [%0], [%1], 16;" :: "r"(dst), "l"(src) : "memory")
#define CP_COMMIT() asm volatile("cp.async.commit_group;" ::: "memory")
#define CP_WAIT0()  asm volatile("cp.async.wait_group 0;" ::: "memory")

// 256B rows = 16x 16B units; swizzle keeps bit3, XORs low3 with row
__device__ __forceinline__ uint32_t swz8(uint32_t u, uint32_t row) {
    return (u & 8u) | ((u ^ row) & 7u);
}

// ---------------- K1: weight transform  U = G g G^T -> fp16 ------------------
__global__ void k_wt(const float* __restrict__ w) {
    int tid = blockIdx.x * 128 + threadIdx.x;   // 16384 threads: (c,o)
    int o = tid & 127;
    int c = tid >> 7;
    const float* g = w + ((size_t)o * CD + c) * 9;
    float gm[3][3];
#pragma unroll
    for (int i = 0; i < 3; i++)
#pragma unroll
        for (int j = 0; j < 3; j++) gm[i][j] = g[i * 3 + j];

    float t[4][3];
#pragma unroll
    for (int k = 0; k < 3; k++) {
        t[0][k] = gm[0][k];
        t[1][k] = 0.5f * (gm[0][k] + gm[1][k] + gm[2][k]);
        t[2][k] = 0.5f * (gm[0][k] - gm[1][k] + gm[2][k]);
        t[3][k] = gm[2][k];
    }
#pragma unroll
    for (int i = 0; i < 4; i++) {
        float u[4];
        u[0] = t[i][0];
        u[1] = 0.5f * (t[i][0] + t[i][1] + t[i][2]);
        u[2] = 0.5f * (t[i][0] - t[i][1] + t[i][2]);
        u[3] = t[i][2];
#pragma unroll
        for (int j = 0; j < 4; j++) {
            int p = i * 4 + j;
            g_Uh[((size_t)(p * OD + o)) * 128 + c] =
                __half_as_ushort(__float2half_rn(u[j]));
        }
    }
}

// ---------------- K2: fully fused transform + GEMM + output -------------------
// CTA: o=128 x tiles=64, 256 threads (8 warps, warp tile 32o x 32t).
// Two half-phases over p (8 planes each): transform V-half into SMEM, then
// GEMM+fold those 8 p. accY persists across halves. Y written once at the end.
// SMEM: A double-buffer 2x32KB @ 0, V 8 p-planes x 16KB @ 64KB. Total 192 KB.
#define A_STG 32768
#define V_OFF 65536
#define FUSE_SMEM (V_OFF + 8 * 16384)   // 192 KB

__global__ void __launch_bounds__(256, 1) k_fused(const float* __restrict__ x,
                                                  const float* __restrict__ bias,
                                                  float* __restrict__ y) {
    extern __shared__ char sm[];
    const uint32_t base = smem_to_u32(sm);
    const int tid = threadIdx.x;
    const int lane = tid & 31;
    const int wid = tid >> 5;
    const int jb = blockIdx.x * 64;
    const int o0 = (wid & 3) * 32;    // 4 o-groups
    const int n0 = (wid >> 2) * 32;   // 2 t-groups

    // Prologue: stage A(p=0) into buffer 0
    {
        const uint4* gA = (const uint4*)g_Uh;
#pragma unroll
        for (int i = 0; i < 8; i++) {
            int g = i * 256 + tid;                 // 2048 chunks (32KB)
            uint32_t row = (uint32_t)g >> 4, u = (uint32_t)g & 15;
            CP16(base + row * 256 + swz8(u, row) * 16, gA + g);
        }
        CP_COMMIT();
    }

    float accY[2][2][2][4][4];   // [a][b][m][nf][j] = 128 regs
#pragma unroll
    for (int a = 0; a < 2; a++)
#pragma unroll
        for (int b = 0; b < 2; b++)
#pragma unroll
            for (int m = 0; m < 2; m++)
#pragma unroll
                for (int nf = 0; nf < 4; nf++)
#pragma unroll
                    for (int j = 0; j < 4; j++) accY[a][b][m][nf][j] = 0.0f;

    const uint32_t rA = (uint32_t)(o0 + (lane & 15));
    const uint32_t uA = (uint32_t)(lane >> 4);
    const uint32_t rB = (uint32_t)(n0 + (lane & 7) + ((lane & 16) >> 1));
    const uint32_t uB = (uint32_t)((lane >> 3) & 1);

    const float AT0[4] = {1.f, 1.f, 1.f, 0.f};
    const float AT1[4] = {0.f, 1.f, -1.f, -1.f};

#pragma unroll 1
    for (int hh = 0; hh < 2; hh++) {
        // ---- transform phase: V planes p = hh*8 .. hh*8+7 into SMEM ----
#pragma unroll 1
        for (int it = 0; it < 16; it++) {
            int idx = it * 8 + wid;          // 0..127 = (c2, tile-half)
            int c2 = idx >> 1;               // channel pair 0..63
            int tl = (idx & 1) * 32 + lane;  // tile 0..63
            int tile = jb + tl;
            int n = tile / TPI;
            int r = tile - n * TPI;
            int ty = r / NT;
            int tx = r - ty * NT;
            int r0 = 2 * ty - 1, c0 = 2 * tx - 1;

            unsigned short h[2][16];
#pragma unroll
            for (int cc = 0; cc < 2; cc++) {
                int c = 2 * c2 + cc;
                const float* xp = x + ((size_t)(n * CD + c)) * (HH * HH);
                float d[4][4];
#pragma unroll
                for (int ii = 0; ii < 4; ii++) {
                    int rr = r0 + ii;
                    bool okr = ((unsigned)rr < HH);
#pragma unroll
                    for (int jj = 0; jj < 4; jj++) {
                        int ccol = c0 + jj;
                        d[ii][jj] = (okr && (unsigned)ccol < HH) ? xp[rr * HH + ccol] : 0.0f;
                    }
                }
                float t[4][4];
#pragma unroll
                for (int j = 0; j < 4; j++) {
                    t[0][j] = d[0][j] - d[2][j];
                    t[1][j] = d[1][j] + d[2][j];
                    t[2][j] = d[2][j] - d[1][j];
                    t[3][j] = d[1][j] - d[3][j];
                }
#pragma unroll
                for (int i = 0; i < 4; i++) {
                    float v0 = t[i][0] - t[i][2];
                    float v1 = t[i][1] + t[i][2];
                    float v2 = t[i][2] - t[i][1];
                    float v3 = t[i][1] - t[i][3];
                    h[cc][i * 4 + 0] = __half_as_ushort(__float2half_rn(v0));
                    h[cc][i * 4 + 1] = __half_as_ushort(__float2half_rn(v1));
                    h[cc][i * 4 + 2] = __half_as_ushort(__float2half_rn(v2));
                    h[cc][i * 4 + 3] = __half_as_ushort(__float2half_rn(v3));
                }
            }
            uint32_t woff = (uint32_t)tl * 256 + swz8((uint32_t)c2 >> 2, (uint32_t)tl) * 16
                            + ((uint32_t)c2 & 3) * 4;
#pragma unroll
            for (int p8 = 0; p8 < 8; p8++) {
                int p = hh * 8 + p8;
                uint32_t pk = (uint32_t)h[0][p] | ((uint32_t)h[1][p] << 16);
                *(uint32_t*)(sm + V_OFF + p8 * 16384 + woff) = pk;
            }
        }
        __syncthreads();   // V half visible (A cp.async still in flight is fine)

        // ---- GEMM + fold over this half's 8 planes ----
#pragma unroll 1
        for (int p8 = 0; p8 < 8; p8++) {
            const int p = hh * 8 + p8;
            CP_WAIT0();
            __syncthreads();

            if (p < 15) {   // stage A(p+1) into the other buffer
                uint32_t nb = base + (uint32_t)((p + 1) & 1) * A_STG;
                const uint4* gA = (const uint4*)(g_Uh + (size_t)(p + 1) * OD * 128);
#pragma unroll
                for (int i = 0; i < 8; i++) {
                    int g = i * 256 + tid;
                    uint32_t row = (uint32_t)g >> 4, u = (uint32_t)g & 15;
                    CP16(nb + row * 256 + swz8(u, row) * 16, gA + g);
                }
                CP_COMMIT();
            }

            const uint32_t aB = base + (uint32_t)(p & 1) * A_STG;
            const uint32_t bB = base + V_OFF + (uint32_t)p8 * 16384;

            float macc[2][4][4];
#pragma unroll
            for (int m = 0; m < 2; m++)
#pragma unroll
                for (int nf = 0; nf < 4; nf++)
#pragma unroll
                    for (int j = 0; j < 4; j++) macc[m][nf][j] = 0.0f;

#pragma unroll
            for (int kc = 0; kc < 8; kc++) {
                uint32_t ah[2][4], bh[4][2];
#pragma unroll
                for (int m = 0; m < 2; m++) {
                    uint32_t r = rA + m * 16;
                    uint32_t u = 2 * kc + uA;
                    LDSM4(ah[m], aB + r * 256 + (swz8(u, r) << 4));
                }
#pragma unroll
                for (int q = 0; q < 2; q++) {
                    uint32_t r = rB + q * 16;
                    uint32_t u = 2 * kc + uB;
                    uint32_t t[4];
                    LDSM4(t, bB + r * 256 + (swz8(u, r) << 4));
                    bh[2 * q][0] = t[0]; bh[2 * q][1] = t[1];
                    bh[2 * q + 1][0] = t[2]; bh[2 * q + 1][1] = t[3];
                }
#pragma unroll
                for (int m = 0; m < 2; m++)
#pragma unroll
                    for (int nf = 0; nf < 4; nf++)
                        MMA_F16(macc[m][nf], ah[m], bh[nf]);
            }

            // fold M[p] into Y_ab with compile-time ±1 coefficients
            const int pi = p >> 2, pj = p & 3;
#pragma unroll
            for (int a = 0; a < 2; a++) {
                const float wa = (a == 0) ? AT0[pi] : AT1[pi];
#pragma unroll
                for (int b = 0; b < 2; b++) {
                    const float wb = (b == 0) ? AT0[pj] : AT1[pj];
                    const float c = wa * wb;
                    if (c != 0.0f) {
#pragma unroll
                        for (int m = 0; m < 2; m++)
#pragma unroll
                            for (int nf = 0; nf < 4; nf++)
#pragma unroll
                                for (int j = 0; j < 4; j++)
                                    accY[a][b][m][nf][j] = fmaf(c, macc[m][nf][j],
                                                                accY[a][b][m][nf][j]);
                    }
                }
            }
            __syncthreads();   // buf(p) consumed; A(p+1) visible next iter
        }
    }

    // Epilogue: bias + direct Y writes
#pragma unroll
    for (int m = 0; m < 2; m++) {
#pragma unroll
        for (int h = 0; h < 2; h++) {
            int o = o0 + m * 16 + (lane >> 2) + h * 8;
            float bv = bias[o];
#pragma unroll
            for (int nf = 0; nf < 4; nf++) {
#pragma unroll
                for (int d = 0; d < 2; d++) {
                    int t = jb + n0 + nf * 8 + (lane & 3) * 2 + d;
                    int n = t / TPI;
                    int r = t - n * TPI;
                    int ty = r / NT;
                    int tx = r - ty * NT;
                    float* yp = y + ((size_t)(n * OD + o) * HH + 2 * ty) * HH + 2 * tx;
                    int j = 2 * h + d;
                    float2 v0 = make_float2(accY[0][0][m][nf][j] + bv,
                                            accY[0][1][m][nf][j] + bv);
                    float2 v1 = make_float2(accY[1][0][m][nf][j] + bv,
                                            accY[1][1][m][nf][j] + bv);
                    *(float2*)yp = v0;
                    *(float2*)(yp + HH) = v1;
                }
            }
        }
    }
}

// ---------------- launch --------------------------------------------------------
extern "C" void kernel_launch(void* const* d_in, const int* in_sizes, int n_in,
                              void* d_out, int out_size) {
    const float* x = (const float*)d_in[0];
    const float* w = (const float*)d_in[1];
    const float* bias = (const float*)d_in[2];
    float* y = (float*)d_out;

    cudaFuncSetAttribute(k_fused, cudaFuncAttributeMaxDynamicSharedMemorySize, FUSE_SMEM);

    k_wt<<<128, 128>>>(w);
    k_fused<<<TILES / 64, 256, FUSE_SMEM>>>(x, bias, y);   // 784 CTAs
}